// round 10
// baseline (speedup 1.0000x reference)
#include <cuda_runtime.h>
#include <math.h>

#define B_    128
#define T_    25
#define HID_  512
#define VOC_  10000
#define VGG_  4096
#define MB_   (T_ * B_)                 // 3200 rows of X / seq
#define LOGITS_ELEMS (B_ * T_ * VOC_)
#define STATE_ELEMS  (2 * B_ * HID_)

typedef unsigned long long ull;

// ---------------- scratch (device globals; no allocation allowed) -----------
__device__ float g_X  [MB_ * HID_];       // embedded tokens [t*B+b][e]
__device__ float g_P  [3 * MB_ * HID_];   // precomputed x-projections (u,r,c)
__device__ float g_s0 [B_ * HID_];        // layer-0 hidden
__device__ float g_s1 [B_ * HID_];        // layer-1 hidden
__device__ float g_gu [B_ * HID_];        // update gate
__device__ float g_grh[B_ * HID_];        // reset_gate * h
__device__ float g_seq[MB_ * HID_];       // all layer-1 states

// ---------------- packed f32x2 helpers --------------------------------------
__device__ __forceinline__ ull pk2(float x) {
    ull r; asm("mov.b64 %0, {%1, %1};" : "=l"(r) : "f"(x)); return r;
}
__device__ __forceinline__ void fma2(ull& c, ull a, ull b) {
    asm("fma.rn.f32x2 %0, %1, %2, %0;" : "+l"(c) : "l"(a), "l"(b));
}
__device__ __forceinline__ ull add2(ull a, ull b) {
    ull r; asm("add.rn.f32x2 %0, %1, %2;" : "=l"(r) : "l"(a), "l"(b)); return r;
}
__device__ __forceinline__ float2 upk(ull v) {
    float2 r; asm("mov.b64 {%0, %1}, %2;" : "=f"(r.x), "=f"(r.y) : "l"(v)); return r;
}
__device__ __forceinline__ float sigf(float z) { return 1.0f / (1.0f + expf(-z)); }

// ============================================================================
// Recurrence GEMM core: 32x32 tile, 256 threads = 8 WARP-AUTONOMOUS k-groups.
// Warp w owns K-slice [w*KG, (w+1)*KG), KG = NCHUNK*16. Each warp stages its
// chunk in a PRIVATE smem slice and synchronizes only with __syncwarp() —
// no block barriers in the main loop (no BAR STS-drain cost; warps overlap
// memory latency independently). Reduction overlays the SAME smem, made safe
// by a __syncthreads() BEFORE the dump (R8's race: dumping into tiles other
// warps were still reading). Static smem stays at 32KB (48KB limit).
// Micro-tile per lane: 4 rows x 8 cols (16 f32x2 accumulators).
// ============================================================================
template <int NCHUNK>
__device__ __forceinline__ bool rec_gemm(
    const float* __restrict__ A0, int lda0, int ka0,
    const float* __restrict__ A1, int lda1,
    const float* __restrict__ W,  int ldw,
    int m0, int n0, ull acc[4][4])
{
    __shared__ __align__(16) ull sraw[4096];     // 32 KB (tiles, then reduction)
    const int tid  = threadIdx.x;
    const int w    = tid >> 5;
    const int lane = tid & 31;
    const int ty   = lane >> 2;      // 0..7 -> rows 4ty..4ty+3
    const int tx   = lane & 3;       // 0..3 -> cols 8tx..8tx+7
    constexpr int KG = NCHUNK * 16;

    float* Af = (float*)(sraw + w * 256);          // [16 kk][32 row] = 2KB
    float* Bf = (float*)(sraw + 2048 + w * 256);   // [16 kk][32 col] = 2KB
    ull*   Bu = (ull*)Bf;

    #pragma unroll
    for (int r = 0; r < 4; r++)
        #pragma unroll
        for (int c = 0; c < 4; c++) acc[r][c] = 0ULL;

    float4 pa[4], pb[4];
    auto loadc = [&](int c) {
        const int kb = w * KG + c * 16;
        const float* A; int lda, ka;
        if (kb < ka0) { A = A0; lda = lda0; ka = kb; }
        else          { A = A1; lda = lda1; ka = kb - ka0; }
        #pragma unroll
        for (int i = 0; i < 4; i++) {
            // A: row = lane, 16 consecutive k per lane
            pa[i] = *(const float4*)(A + (size_t)(m0 + lane) * lda + ka + (i << 2));
            // B: 2 lanes cover one 32-col row
            const int idx = lane * 4 + i;
            pb[i] = *(const float4*)(W + (size_t)(kb + (idx >> 3)) * ldw + n0 + ((idx & 7) << 2));
        }
    };

    loadc(0);
    for (int c = 0; c < NCHUNK; c++) {
        __syncwarp();                              // prior chunk's reads done
        #pragma unroll
        for (int i = 0; i < 4; i++) {
            // A transposed store: Af[kk][row]
            Af[((i << 2) + 0) * 32 + lane] = pa[i].x;
            Af[((i << 2) + 1) * 32 + lane] = pa[i].y;
            Af[((i << 2) + 2) * 32 + lane] = pa[i].z;
            Af[((i << 2) + 3) * 32 + lane] = pa[i].w;
            const int idx = lane * 4 + i;
            *(float4*)&Bf[(idx >> 3) * 32 + ((idx & 7) << 2)] = pb[i];
        }
        __syncwarp();                              // stores visible to warp
        if (c + 1 < NCHUNK) loadc(c + 1);
        #pragma unroll
        for (int kk = 0; kk < 16; kk++) {
            const float4 a = *(const float4*)&Af[kk * 32 + (ty << 2)];
            const ull b0 = Bu[kk * 16 + tx * 4 + 0];
            const ull b1 = Bu[kk * 16 + tx * 4 + 1];
            const ull b2 = Bu[kk * 16 + tx * 4 + 2];
            const ull b3 = Bu[kk * 16 + tx * 4 + 3];
            ull ar;
            ar = pk2(a.x);
            fma2(acc[0][0], ar, b0); fma2(acc[0][1], ar, b1);
            fma2(acc[0][2], ar, b2); fma2(acc[0][3], ar, b3);
            ar = pk2(a.y);
            fma2(acc[1][0], ar, b0); fma2(acc[1][1], ar, b1);
            fma2(acc[1][2], ar, b2); fma2(acc[1][3], ar, b3);
            ar = pk2(a.z);
            fma2(acc[2][0], ar, b0); fma2(acc[2][1], ar, b1);
            fma2(acc[2][2], ar, b2); fma2(acc[2][3], ar, b3);
            ar = pk2(a.w);
            fma2(acc[3][0], ar, b0); fma2(acc[3][1], ar, b1);
            fma2(acc[3][2], ar, b2); fma2(acc[3][3], ar, b3);
        }
    }

    // All warps must be done READING their tiles before anyone overwrites
    // sraw with accumulator dumps (this barrier is what R8 was missing).
    __syncthreads();
    if (w) {
        ull* p = sraw + (size_t)(((w - 1) << 5) + lane) * 17;   // x17 pad: banks
        #pragma unroll
        for (int r = 0; r < 4; r++)
            #pragma unroll
            for (int c = 0; c < 4; c++) p[r * 4 + c] = acc[r][c];
    }
    __syncthreads();
    if (w == 0) {
        #pragma unroll
        for (int ww = 0; ww < 7; ww++) {
            const ull* p = sraw + (size_t)((ww << 5) + lane) * 17;
            #pragma unroll
            for (int r = 0; r < 4; r++)
                #pragma unroll
                for (int c = 0; c < 4; c++) acc[r][c] = add2(acc[r][c], p[r * 4 + c]);
        }
    }
    return w == 0;
}

// ---------------- GRU gates (u and r fused via blockIdx.y) ------------------
template <int NCHUNK>
__global__ __launch_bounds__(256) void k_gates(
    const float* __restrict__ A0, const float* __restrict__ A1, int ka0,
    const float* __restrict__ Wu, const float* __restrict__ bu,
    const float* __restrict__ Wr, const float* __restrict__ br,
    const float* __restrict__ Pu, const float* __restrict__ Pr,
    const float* __restrict__ h)
{
    const int m0 = blockIdx.x * 32;
    const int nc = blockIdx.y * 32;
    const bool isU = nc < HID_;
    const float* W    = isU ? Wu : Wr;
    const float* bias = isU ? bu : br;
    const float* P    = isU ? Pu : Pr;
    const int n0 = isU ? nc : nc - HID_;

    ull acc[4][4];
    if (!rec_gemm<NCHUNK>(A0, HID_, ka0, A1, HID_, W, HID_, m0, n0, acc)) return;

    const int lane = threadIdx.x & 31;
    const int ty = lane >> 2, tx = lane & 3;
    #pragma unroll
    for (int r = 0; r < 4; r++) {
        const int row = m0 + (ty << 2) + r;
        #pragma unroll
        for (int cp = 0; cp < 4; cp++) {
            const float2 v = upk(acc[r][cp]);
            const float vv[2] = {v.x, v.y};
            #pragma unroll
            for (int s = 0; s < 2; s++) {
                const int c = n0 + (tx << 3) + (cp << 1) + s;
                float val = vv[s] + bias[c];
                if (P) val += P[row * HID_ + c];
                const float sg = sigf(val);
                if (isU) g_gu[row * HID_ + c] = sg;
                else     g_grh[row * HID_ + c] = sg * h[row * HID_ + c];
            }
        }
    }
}

// ---------------- GRU candidate + state update ------------------------------
template <int NCHUNK>
__global__ __launch_bounds__(256) void k_cand(
    const float* __restrict__ A0, const float* __restrict__ A1, int ka0,
    const float* __restrict__ Wc, const float* __restrict__ bc,
    const float* __restrict__ Pc,
    float* __restrict__ h, float* __restrict__ seq)
{
    const int m0 = blockIdx.x * 32;
    const int n0 = blockIdx.y * 32;

    ull acc[4][4];
    if (!rec_gemm<NCHUNK>(A0, HID_, ka0, A1, HID_, Wc, HID_, m0, n0, acc)) return;

    const int lane = threadIdx.x & 31;
    const int ty = lane >> 2, tx = lane & 3;
    #pragma unroll
    for (int r = 0; r < 4; r++) {
        const int row = m0 + (ty << 2) + r;
        #pragma unroll
        for (int cp = 0; cp < 4; cp++) {
            const float2 v = upk(acc[r][cp]);
            const float vv[2] = {v.x, v.y};
            #pragma unroll
            for (int s = 0; s < 2; s++) {
                const int c = n0 + (tx << 3) + (cp << 1) + s;
                float val = vv[s] + bc[c];
                if (Pc) val += Pc[row * HID_ + c];
                const float hh = tanhf(val);
                const float gg = g_gu[row * HID_ + c];
                const float hn = gg * h[row * HID_ + c] + (1.0f - gg) * hh;
                h[row * HID_ + c] = hn;
                if (seq) seq[row * HID_ + c] = hn;
            }
        }
    }
}

// ---------------- h0 = tanh(vgg @ W_in + b_in) ------------------------------
__global__ __launch_bounds__(256) void k_h0(
    const float* __restrict__ vgg, const float* __restrict__ W_in,
    const float* __restrict__ b_in)
{
    const int m0 = blockIdx.x * 32;
    const int n0 = blockIdx.y * 32;

    ull acc[4][4];
    if (!rec_gemm<32>(vgg, VGG_, VGG_, vgg, VGG_, W_in, HID_, m0, n0, acc)) return;

    const int lane = threadIdx.x & 31;
    const int ty = lane >> 2, tx = lane & 3;
    #pragma unroll
    for (int r = 0; r < 4; r++) {
        const int row = m0 + (ty << 2) + r;
        #pragma unroll
        for (int cp = 0; cp < 4; cp++) {
            const float2 v = upk(acc[r][cp]);
            const float vv[2] = {v.x, v.y};
            #pragma unroll
            for (int s = 0; s < 2; s++) {
                const int c = n0 + (tx << 3) + (cp << 1) + s;
                const float t = tanhf(vv[s] + b_in[c]);
                g_s0[row * HID_ + c] = t;
                g_s1[row * HID_ + c] = t;
            }
        }
    }
}

// ============================================================================
// Big parallel GEMM core: 64x64 tile, 128 threads, micro-tile 4x8,
// register-prefetch double buffering. Used by logits and precompute.
// K fixed at 512. (Unchanged — controlled experiment.)
// ============================================================================
template <bool GUARD>
__device__ __forceinline__ void big_gemm(
    const float* __restrict__ A, int lda,
    const float* __restrict__ W, int ldw, int nmax,
    int m0, int n0, ull acc[4][4])
{
    __shared__ __align__(16) float As[16][64];
    __shared__ __align__(16) float Bs[16][64];
    const int tid = threadIdx.x;
    const int ty = tid >> 3, tx = tid & 7;

    #pragma unroll
    for (int r = 0; r < 4; r++)
        #pragma unroll
        for (int c = 0; c < 4; c++) acc[r][c] = 0ULL;

    float4 pa[2], pb[2];
    auto loadc = [&](int k0) {
        #pragma unroll
        for (int i = 0; i < 2; i++) {
            const int idx = tid * 2 + i;
            pa[i] = *(const float4*)(A + (size_t)(m0 + (idx >> 2)) * lda + k0 + ((idx & 3) << 2));
            const int kr = idx >> 4, c4 = (idx & 15) << 2;
            const int gc = n0 + c4;
            const float* Wr = W + (size_t)(k0 + kr) * ldw;
            if (!GUARD || gc + 3 < nmax) {
                pb[i] = *(const float4*)(Wr + gc);
            } else {
                pb[i].x = (gc + 0 < nmax) ? Wr[gc + 0] : 0.0f;
                pb[i].y = (gc + 1 < nmax) ? Wr[gc + 1] : 0.0f;
                pb[i].z = (gc + 2 < nmax) ? Wr[gc + 2] : 0.0f;
                pb[i].w = (gc + 3 < nmax) ? Wr[gc + 3] : 0.0f;
            }
        }
    };

    loadc(0);
    for (int k0 = 0; k0 < HID_; k0 += 16) {
        #pragma unroll
        for (int i = 0; i < 2; i++) {
            const int idx = tid * 2 + i;
            const int row = idx >> 2, kc = (idx & 3) << 2;
            As[kc + 0][row] = pa[i].x;
            As[kc + 1][row] = pa[i].y;
            As[kc + 2][row] = pa[i].z;
            As[kc + 3][row] = pa[i].w;
            *(float4*)&Bs[idx >> 4][(idx & 15) << 2] = pb[i];
        }
        __syncthreads();
        if (k0 + 16 < HID_) loadc(k0 + 16);
        #pragma unroll
        for (int kk = 0; kk < 16; kk++) {
            const float4 a = *(const float4*)&As[kk][ty << 2];
            const ull* br = (const ull*)Bs[kk];
            const ull b0 = br[tx * 4 + 0], b1 = br[tx * 4 + 1];
            const ull b2 = br[tx * 4 + 2], b3 = br[tx * 4 + 3];
            ull ar;
            ar = pk2(a.x);
            fma2(acc[0][0], ar, b0); fma2(acc[0][1], ar, b1);
            fma2(acc[0][2], ar, b2); fma2(acc[0][3], ar, b3);
            ar = pk2(a.y);
            fma2(acc[1][0], ar, b0); fma2(acc[1][1], ar, b1);
            fma2(acc[1][2], ar, b2); fma2(acc[1][3], ar, b3);
            ar = pk2(a.z);
            fma2(acc[2][0], ar, b0); fma2(acc[2][1], ar, b1);
            fma2(acc[2][2], ar, b2); fma2(acc[2][3], ar, b3);
            ar = pk2(a.w);
            fma2(acc[3][0], ar, b0); fma2(acc[3][1], ar, b1);
            fma2(acc[3][2], ar, b2); fma2(acc[3][3], ar, b3);
        }
        __syncthreads();
    }
}

// ---------------- precompute: P[z] = X @ Wz[0:512]  (z = u0, r0, c0) --------
__global__ __launch_bounds__(128) void k_prec(
    const float* __restrict__ Wu0, const float* __restrict__ Wr0,
    const float* __restrict__ Wc0)
{
    const int z = blockIdx.z;
    const float* W = (z == 0) ? Wu0 : ((z == 1) ? Wr0 : Wc0);
    float* outp = g_P + (size_t)z * MB_ * HID_;
    const int m0 = blockIdx.x * 64;
    const int n0 = blockIdx.y * 64;

    ull acc[4][4];
    big_gemm<false>(g_X, HID_, W, HID_, HID_, m0, n0, acc);

    const int tid = threadIdx.x;
    const int ty = tid >> 3, tx = tid & 7;
    #pragma unroll
    for (int r = 0; r < 4; r++) {
        const int row = m0 + (ty << 2) + r;
        #pragma unroll
        for (int cp = 0; cp < 4; cp++) {
            const float2 v = upk(acc[r][cp]);
            const int c = n0 + (tx << 3) + (cp << 1);
            outp[(size_t)row * HID_ + c]     = v.x;
            outp[(size_t)row * HID_ + c + 1] = v.y;
        }
    }
}

// ---------------- logits: g_seq[3200,512] @ W_out[512,10000] + b_out --------
__global__ __launch_bounds__(128) void k_logits(
    const float* __restrict__ Wo, const float* __restrict__ bo,
    float* __restrict__ out)
{
    const int m0 = blockIdx.x * 64;
    const int n0 = blockIdx.y * 64;

    ull acc[4][4];
    big_gemm<true>(g_seq, HID_, Wo, VOC_, VOC_, m0, n0, acc);

    const int tid = threadIdx.x;
    const int ty = tid >> 3, tx = tid & 7;
    #pragma unroll
    for (int r = 0; r < 4; r++) {
        const int row = m0 + (ty << 2) + r;   // row = t*B + b
        const int tt = row >> 7;
        const int bb = row & (B_ - 1);
        const size_t obase = (size_t)(bb * T_ + tt) * VOC_;
        #pragma unroll
        for (int cp = 0; cp < 4; cp++) {
            const float2 v = upk(acc[r][cp]);
            const float vv[2] = {v.x, v.y};
            #pragma unroll
            for (int s = 0; s < 2; s++) {
                const int c = n0 + (tx << 3) + (cp << 1) + s;
                if (c < VOC_) out[obase + c] = vv[s] + bo[c];
            }
        }
    }
}

// ---------------- embedding gather ------------------------------------------
__global__ void k_embed(const float* __restrict__ emb, const int* __restrict__ tok)
{
    const int i = blockIdx.x * 256 + threadIdx.x;      // float4 index
    if (i >= MB_ * (HID_ / 4)) return;
    const int e4 = i & 127;
    const int tb = i >> 7;                             // t*B + b
    const int t = tb >> 7;
    const int b = tb & (B_ - 1);
    const int tk = tok[b * T_ + t];
    ((float4*)g_X)[i] = ((const float4*)emb)[(size_t)tk * (HID_ / 4) + e4];
}

// ---------------- final state copy ------------------------------------------
__global__ void k_state(float* __restrict__ out)
{
    const int i = blockIdx.x * 256 + threadIdx.x;
    if (i >= B_ * HID_) return;
    out[LOGITS_ELEMS + i]             = g_s0[i];
    out[LOGITS_ELEMS + B_ * HID_ + i] = g_s1[i];
}

// ---------------- launch -----------------------------------------------------
extern "C" void kernel_launch(void* const* d_in, const int* in_sizes, int n_in,
                              void* d_out, int out_size)
{
    const float* vgg  = (const float*)d_in[0];
    const int*   tok  = (const int*)  d_in[1];
    // d_in[2] = is_train (unused)
    const float* emb  = (const float*)d_in[3];
    const float* W_in = (const float*)d_in[4];
    const float* b_in = (const float*)d_in[5];
    const float* Wu0  = (const float*)d_in[6];
    const float* bu0  = (const float*)d_in[7];
    const float* Wr0  = (const float*)d_in[8];
    const float* br0  = (const float*)d_in[9];
    const float* Wc0  = (const float*)d_in[10];
    const float* bc0  = (const float*)d_in[11];
    const float* Wu1  = (const float*)d_in[12];
    const float* bu1  = (const float*)d_in[13];
    const float* Wr1  = (const float*)d_in[14];
    const float* br1  = (const float*)d_in[15];
    const float* Wc1  = (const float*)d_in[16];
    const float* bc1  = (const float*)d_in[17];
    const float* Wo   = (const float*)d_in[18];
    const float* bo   = (const float*)d_in[19];
    float* out = (float*)d_out;

    void *pS0, *pS1, *pSeq, *pGrh, *pP;
    cudaGetSymbolAddress(&pS0,  g_s0);
    cudaGetSymbolAddress(&pS1,  g_s1);
    cudaGetSymbolAddress(&pSeq, g_seq);
    cudaGetSymbolAddress(&pGrh, g_grh);
    cudaGetSymbolAddress(&pP,   g_P);
    float* s0  = (float*)pS0;
    float* s1  = (float*)pS1;
    float* seq = (float*)pSeq;
    float* grh = (float*)pGrh;
    float* P   = (float*)pP;

    k_embed<<<(MB_ * (HID_ / 4) + 255) / 256, 256>>>(emb, tok);
    k_prec<<<dim3(MB_ / 64, HID_ / 64, 3), 128>>>(Wu0, Wr0, Wc0);
    k_h0<<<dim3(B_ / 32, HID_ / 32), 256>>>(vgg, W_in, b_in);

    const dim3 gGates(B_ / 32, (2 * HID_) / 32);   // 4 x 32 = 128 CTAs
    const dim3 gCand (B_ / 32, HID_ / 32);         // 4 x 16 =  64 CTAs
    const size_t plane = (size_t)MB_ * HID_;
    const float* Wu0h = Wu0 + (size_t)HID_ * HID_;  // h-part rows of layer-0 W
    const float* Wr0h = Wr0 + (size_t)HID_ * HID_;
    const float* Wc0h = Wc0 + (size_t)HID_ * HID_;

    for (int t = 0; t < T_; t++) {
        const float* Pu = P + 0 * plane + (size_t)t * B_ * HID_;
        const float* Pr = P + 1 * plane + (size_t)t * B_ * HID_;
        const float* Pc = P + 2 * plane + (size_t)t * B_ * HID_;
        // layer 0: K = 512 (h only; x-part precomputed)
        k_gates<4><<<gGates, 256>>>(s0, s0, HID_, Wu0h, bu0, Wr0h, br0, Pu, Pr, s0);
        k_cand <4><<<gCand, 256>>>(grh, grh, HID_, Wc0h, bc0, Pc, s0, (float*)0);
        // layer 1: K = 1024 ([x=s0 | h=s1])
        k_gates<8><<<gGates, 256>>>(s0, s1, HID_, Wu1, bu1, Wr1, br1, (float*)0, (float*)0, s1);
        k_cand <8><<<gCand, 256>>>(s0, grh, HID_, Wc1, bc1, (float*)0, s1,
                                   seq + (size_t)t * B_ * HID_);
    }

    k_logits<<<dim3(MB_ / 64, (VOC_ + 63) / 64), 128>>>(Wo, bo, out);
    if (out_size >= LOGITS_ELEMS + STATE_ELEMS)
        k_state<<<(B_ * HID_ + 255) / 256, 256>>>(out);
}

// round 14
// speedup vs baseline: 1.7357x; 1.7357x over previous
#include <cuda_runtime.h>
#include <math.h>

#define B_    128
#define T_    25
#define HID_  512
#define VOC_  10000
#define VGG_  4096
#define MB_   (T_ * B_)                 // 3200 rows of X / seq
#define LOGITS_ELEMS (B_ * T_ * VOC_)
#define STATE_ELEMS  (2 * B_ * HID_)

typedef unsigned long long ull;

// ---------------- scratch (device globals; no allocation allowed) -----------
__device__ float g_X  [MB_ * HID_];       // embedded tokens [t*B+b][e]
__device__ float g_P  [3 * MB_ * HID_];   // precomputed x-projections (u,r,c)
__device__ float g_s0 [B_ * HID_];        // layer-0 hidden
__device__ float g_s1 [B_ * HID_];        // layer-1 hidden
__device__ float g_gu [B_ * HID_];        // update gate
__device__ float g_grh[B_ * HID_];        // reset_gate * h
__device__ float g_seq[MB_ * HID_];       // all layer-1 states

// ---------------- packed f32x2 helpers --------------------------------------
__device__ __forceinline__ ull pk2(float x) {
    ull r; asm("mov.b64 %0, {%1, %1};" : "=l"(r) : "f"(x)); return r;
}
__device__ __forceinline__ void fma2(ull& c, ull a, ull b) {
    asm("fma.rn.f32x2 %0, %1, %2, %0;" : "+l"(c) : "l"(a), "l"(b));
}
__device__ __forceinline__ ull add2(ull a, ull b) {
    ull r; asm("add.rn.f32x2 %0, %1, %2;" : "=l"(r) : "l"(a), "l"(b)); return r;
}
__device__ __forceinline__ float2 upk(ull v) {
    float2 r; asm("mov.b64 {%0, %1}, %2;" : "=f"(r.x), "=f"(r.y) : "l"(v)); return r;
}
__device__ __forceinline__ float sigf(float z) { return 1.0f / (1.0f + expf(-z)); }

// ============================================================================
// Recurrence GEMM core: main loop is the EXACT measured-good (3436us) version
// (32x32 tile, 256 thr = 8 k-groups x 32 lanes, block-lockstep, register
// prefetch). NEW: flat dump + all-thread reduction replaces the 6-barrier
// tree + single-warp epilogue. On return EVERY thread holds the summed
// results for 4 consecutive output columns of one row:
//   row = m0 + ((tid>>3)>>2)*4 + ((tid&7)>>1)      [derived below]
//   col = n0 + ((tid>>3)&3)*8 + ((tid&7)&1)*4      -> out covers col..col+3
// Mapping: epilogue index k = 2*tid (+1); lane L = k>>4; j = k&15;
//   r = j>>2, c = j&3; row = m0 + (L>>2)*4 + r; col = n0 + (L&3)*8 + c*2.
// out[0] = f32x2 at (row, col..col+1), out[1] = (row, col+2..col+3).
// ============================================================================
#define DUMP17 (8 * 32 * 17)            // padded dump region (4352 ull)

template <int NCHUNK>
__device__ __forceinline__ void rec_gemm(
    const float* __restrict__ A0, int lda0, int ka0,
    const float* __restrict__ A1, int lda1,
    const float* __restrict__ W,  int ldw,
    int m0, int n0, ull out[2])
{
    __shared__ __align__(16) ull sraw[DUMP17];   // tiles use first 4096; 34KB
    const int tid  = threadIdx.x;
    const int g    = tid >> 5;
    const int lane = tid & 31;
    const int ty   = lane >> 2;
    const int tx   = lane & 3;
    constexpr int KG = NCHUNK * 16;

    float* Af = (float*)(sraw + g * 256);          // [16 kk][32 row] = 2KB
    float* Bf = (float*)(sraw + 2048 + g * 256);   // [16 kk][32 col] = 2KB
    ull*   Bu = (ull*)Bf;

    ull acc[4][4];
    #pragma unroll
    for (int r = 0; r < 4; r++)
        #pragma unroll
        for (int c = 0; c < 4; c++) acc[r][c] = 0ULL;

    float4 pa[4], pb[4];
    auto loadc = [&](int c) {
        const int kb = g * KG + c * 16;
        const float* A; int lda, ka;
        if (kb < ka0) { A = A0; lda = lda0; ka = kb; }
        else          { A = A1; lda = lda1; ka = kb - ka0; }
        #pragma unroll
        for (int i = 0; i < 4; i++) {
            const int idx = lane * 4 + i;
            pa[i] = *(const float4*)(A + (size_t)(m0 + (idx >> 2)) * lda + ka + ((idx & 3) << 2));
            pb[i] = *(const float4*)(W + (size_t)(kb + (idx >> 3)) * ldw + n0 + ((idx & 7) << 2));
        }
    };

    loadc(0);
    for (int c = 0; c < NCHUNK; c++) {
        #pragma unroll
        for (int i = 0; i < 4; i++) {
            const int idx = lane * 4 + i;
            const int row = idx >> 2, kc = (idx & 3) << 2;
            Af[(kc + 0) * 32 + row] = pa[i].x;
            Af[(kc + 1) * 32 + row] = pa[i].y;
            Af[(kc + 2) * 32 + row] = pa[i].z;
            Af[(kc + 3) * 32 + row] = pa[i].w;
            *(float4*)&Bf[(idx >> 3) * 32 + ((idx & 7) << 2)] = pb[i];
        }
        __syncthreads();
        if (c + 1 < NCHUNK) loadc(c + 1);
        #pragma unroll
        for (int kk = 0; kk < 16; kk++) {
            const float4 a = *(const float4*)&Af[kk * 32 + (ty << 2)];
            const ull b0 = Bu[kk * 16 + tx * 4 + 0];
            const ull b1 = Bu[kk * 16 + tx * 4 + 1];
            const ull b2 = Bu[kk * 16 + tx * 4 + 2];
            const ull b3 = Bu[kk * 16 + tx * 4 + 3];
            ull ar;
            ar = pk2(a.x);
            fma2(acc[0][0], ar, b0); fma2(acc[0][1], ar, b1);
            fma2(acc[0][2], ar, b2); fma2(acc[0][3], ar, b3);
            ar = pk2(a.y);
            fma2(acc[1][0], ar, b0); fma2(acc[1][1], ar, b1);
            fma2(acc[1][2], ar, b2); fma2(acc[1][3], ar, b3);
            ar = pk2(a.z);
            fma2(acc[2][0], ar, b0); fma2(acc[2][1], ar, b1);
            fma2(acc[2][2], ar, b2); fma2(acc[2][3], ar, b3);
            ar = pk2(a.w);
            fma2(acc[3][0], ar, b0); fma2(acc[3][1], ar, b1);
            fma2(acc[3][2], ar, b2); fma2(acc[3][3], ar, b3);
        }
        __syncthreads();
    }

    // flat dump (stride-17 pad) -> one barrier -> every thread gathers its
    // 2 ull (= 4 consecutive output columns) summed over the 8 k-groups.
    {
        ull* p = sraw + (size_t)((g << 5) + lane) * 17;
        #pragma unroll
        for (int r = 0; r < 4; r++)
            #pragma unroll
            for (int c = 0; c < 4; c++) p[r * 4 + c] = acc[r][c];
    }
    __syncthreads();
    {
        const int L = tid >> 3;
        const int j0 = (tid & 7) << 1;
        ull s0 = 0ULL, s1 = 0ULL;
        #pragma unroll
        for (int ww = 0; ww < 8; ww++) {
            const ull* p = sraw + (size_t)((ww << 5) + L) * 17 + j0;
            s0 = add2(s0, p[0]);
            s1 = add2(s1, p[1]);
        }
        out[0] = s0;
        out[1] = s1;
    }
}

// Per-thread output coordinates for the flat epilogue.
__device__ __forceinline__ void epi_coord(int m0, int n0, int& row, int& col)
{
    const int tid = threadIdx.x;
    const int L  = tid >> 3;
    const int j0 = (tid & 7) << 1;
    row = m0 + ((L >> 2) << 2) + (j0 >> 2);
    col = n0 + ((L & 3) << 3) + ((j0 & 3) << 1);
}

// ---------------- GRU gates (u and r fused via blockIdx.y) ------------------
template <int NCHUNK>
__global__ __launch_bounds__(256) void k_gates(
    const float* __restrict__ A0, const float* __restrict__ A1, int ka0,
    const float* __restrict__ Wu, const float* __restrict__ bu,
    const float* __restrict__ Wr, const float* __restrict__ br,
    const float* __restrict__ Pu, const float* __restrict__ Pr,
    const float* __restrict__ h)
{
    const int m0 = blockIdx.x * 32;
    const int nc = blockIdx.y * 32;
    const bool isU = nc < HID_;
    const float* W    = isU ? Wu : Wr;
    const float* bias = isU ? bu : br;
    const float* P    = isU ? Pu : Pr;
    const int n0 = isU ? nc : nc - HID_;

    ull out[2];
    rec_gemm<NCHUNK>(A0, HID_, ka0, A1, HID_, W, HID_, m0, n0, out);

    int row, col;
    epi_coord(m0, n0, row, col);
    const float2 v0 = upk(out[0]);
    const float2 v1 = upk(out[1]);
    const float4 bb = *(const float4*)&bias[col];
    float4 val = make_float4(v0.x + bb.x, v0.y + bb.y, v1.x + bb.z, v1.y + bb.w);
    if (P) {
        const float4 pp = *(const float4*)&P[row * HID_ + col];
        val.x += pp.x; val.y += pp.y; val.z += pp.z; val.w += pp.w;
    }
    val.x = sigf(val.x); val.y = sigf(val.y);
    val.z = sigf(val.z); val.w = sigf(val.w);
    if (isU) {
        *(float4*)&g_gu[row * HID_ + col] = val;
    } else {
        const float4 hh = *(const float4*)&h[row * HID_ + col];
        val.x *= hh.x; val.y *= hh.y; val.z *= hh.z; val.w *= hh.w;
        *(float4*)&g_grh[row * HID_ + col] = val;
    }
}

// ---------------- GRU candidate + state update ------------------------------
template <int NCHUNK>
__global__ __launch_bounds__(256) void k_cand(
    const float* __restrict__ A0, const float* __restrict__ A1, int ka0,
    const float* __restrict__ Wc, const float* __restrict__ bc,
    const float* __restrict__ Pc,
    float* __restrict__ h, float* __restrict__ seq)
{
    const int m0 = blockIdx.x * 32;
    const int n0 = blockIdx.y * 32;

    ull out[2];
    rec_gemm<NCHUNK>(A0, HID_, ka0, A1, HID_, Wc, HID_, m0, n0, out);

    int row, col;
    epi_coord(m0, n0, row, col);
    const float2 v0 = upk(out[0]);
    const float2 v1 = upk(out[1]);
    const float4 bb = *(const float4*)&bc[col];
    float4 val = make_float4(v0.x + bb.x, v0.y + bb.y, v1.x + bb.z, v1.y + bb.w);
    if (Pc) {
        const float4 pp = *(const float4*)&Pc[row * HID_ + col];
        val.x += pp.x; val.y += pp.y; val.z += pp.z; val.w += pp.w;
    }
    const float4 gg = *(const float4*)&g_gu[row * HID_ + col];
    const float4 hh = *(const float4*)&h[row * HID_ + col];
    float4 hn;
    hn.x = gg.x * hh.x + (1.0f - gg.x) * tanhf(val.x);
    hn.y = gg.y * hh.y + (1.0f - gg.y) * tanhf(val.y);
    hn.z = gg.z * hh.z + (1.0f - gg.z) * tanhf(val.z);
    hn.w = gg.w * hh.w + (1.0f - gg.w) * tanhf(val.w);
    *(float4*)&h[row * HID_ + col] = hn;
    if (seq) *(float4*)&seq[row * HID_ + col] = hn;
}

// ---------------- h0 = tanh(vgg @ W_in + b_in) ------------------------------
__global__ __launch_bounds__(256) void k_h0(
    const float* __restrict__ vgg, const float* __restrict__ W_in,
    const float* __restrict__ b_in)
{
    const int m0 = blockIdx.x * 32;
    const int n0 = blockIdx.y * 32;

    ull out[2];
    rec_gemm<32>(vgg, VGG_, VGG_, vgg, VGG_, W_in, HID_, m0, n0, out);

    int row, col;
    epi_coord(m0, n0, row, col);
    const float2 v0 = upk(out[0]);
    const float2 v1 = upk(out[1]);
    const float4 bb = *(const float4*)&b_in[col];
    float4 val;
    val.x = tanhf(v0.x + bb.x);
    val.y = tanhf(v0.y + bb.y);
    val.z = tanhf(v1.x + bb.z);
    val.w = tanhf(v1.y + bb.w);
    *(float4*)&g_s0[row * HID_ + col] = val;
    *(float4*)&g_s1[row * HID_ + col] = val;
}

// ============================================================================
// Big parallel GEMM core: 64x64 tile, 128 threads, micro-tile 4x8 (unchanged).
// ============================================================================
template <bool GUARD>
__device__ __forceinline__ void big_gemm(
    const float* __restrict__ A, int lda,
    const float* __restrict__ W, int ldw, int nmax,
    int m0, int n0, ull acc[4][4])
{
    __shared__ __align__(16) float As[16][64];
    __shared__ __align__(16) float Bs[16][64];
    const int tid = threadIdx.x;
    const int ty = tid >> 3, tx = tid & 7;

    #pragma unroll
    for (int r = 0; r < 4; r++)
        #pragma unroll
        for (int c = 0; c < 4; c++) acc[r][c] = 0ULL;

    float4 pa[2], pb[2];
    auto loadc = [&](int k0) {
        #pragma unroll
        for (int i = 0; i < 2; i++) {
            const int idx = tid * 2 + i;
            pa[i] = *(const float4*)(A + (size_t)(m0 + (idx >> 2)) * lda + k0 + ((idx & 3) << 2));
            const int kr = idx >> 4, c4 = (idx & 15) << 2;
            const int gc = n0 + c4;
            const float* Wr = W + (size_t)(k0 + kr) * ldw;
            if (!GUARD || gc + 3 < nmax) {
                pb[i] = *(const float4*)(Wr + gc);
            } else {
                pb[i].x = (gc + 0 < nmax) ? Wr[gc + 0] : 0.0f;
                pb[i].y = (gc + 1 < nmax) ? Wr[gc + 1] : 0.0f;
                pb[i].z = (gc + 2 < nmax) ? Wr[gc + 2] : 0.0f;
                pb[i].w = (gc + 3 < nmax) ? Wr[gc + 3] : 0.0f;
            }
        }
    };

    loadc(0);
    for (int k0 = 0; k0 < HID_; k0 += 16) {
        #pragma unroll
        for (int i = 0; i < 2; i++) {
            const int idx = tid * 2 + i;
            const int row = idx >> 2, kc = (idx & 3) << 2;
            As[kc + 0][row] = pa[i].x;
            As[kc + 1][row] = pa[i].y;
            As[kc + 2][row] = pa[i].z;
            As[kc + 3][row] = pa[i].w;
            *(float4*)&Bs[idx >> 4][(idx & 15) << 2] = pb[i];
        }
        __syncthreads();
        if (k0 + 16 < HID_) loadc(k0 + 16);
        #pragma unroll
        for (int kk = 0; kk < 16; kk++) {
            const float4 a = *(const float4*)&As[kk][ty << 2];
            const ull* br = (const ull*)Bs[kk];
            const ull b0 = br[tx * 4 + 0], b1 = br[tx * 4 + 1];
            const ull b2 = br[tx * 4 + 2], b3 = br[tx * 4 + 3];
            ull ar;
            ar = pk2(a.x);
            fma2(acc[0][0], ar, b0); fma2(acc[0][1], ar, b1);
            fma2(acc[0][2], ar, b2); fma2(acc[0][3], ar, b3);
            ar = pk2(a.y);
            fma2(acc[1][0], ar, b0); fma2(acc[1][1], ar, b1);
            fma2(acc[1][2], ar, b2); fma2(acc[1][3], ar, b3);
            ar = pk2(a.z);
            fma2(acc[2][0], ar, b0); fma2(acc[2][1], ar, b1);
            fma2(acc[2][2], ar, b2); fma2(acc[2][3], ar, b3);
            ar = pk2(a.w);
            fma2(acc[3][0], ar, b0); fma2(acc[3][1], ar, b1);
            fma2(acc[3][2], ar, b2); fma2(acc[3][3], ar, b3);
        }
        __syncthreads();
    }
}

// ---------------- precompute: P[z] = X @ Wz[0:512]  (z = u0, r0, c0) --------
__global__ __launch_bounds__(128) void k_prec(
    const float* __restrict__ Wu0, const float* __restrict__ Wr0,
    const float* __restrict__ Wc0)
{
    const int z = blockIdx.z;
    const float* W = (z == 0) ? Wu0 : ((z == 1) ? Wr0 : Wc0);
    float* outp = g_P + (size_t)z * MB_ * HID_;
    const int m0 = blockIdx.x * 64;
    const int n0 = blockIdx.y * 64;

    ull acc[4][4];
    big_gemm<false>(g_X, HID_, W, HID_, HID_, m0, n0, acc);

    const int tid = threadIdx.x;
    const int ty = tid >> 3, tx = tid & 7;
    #pragma unroll
    for (int r = 0; r < 4; r++) {
        const int row = m0 + (ty << 2) + r;
        #pragma unroll
        for (int cp = 0; cp < 4; cp++) {
            const float2 v = upk(acc[r][cp]);
            const int c = n0 + (tx << 3) + (cp << 1);
            outp[(size_t)row * HID_ + c]     = v.x;
            outp[(size_t)row * HID_ + c + 1] = v.y;
        }
    }
}

// ---------------- logits: g_seq[3200,512] @ W_out[512,10000] + b_out --------
__global__ __launch_bounds__(128) void k_logits(
    const float* __restrict__ Wo, const float* __restrict__ bo,
    float* __restrict__ out)
{
    const int m0 = blockIdx.x * 64;
    const int n0 = blockIdx.y * 64;

    ull acc[4][4];
    big_gemm<true>(g_seq, HID_, Wo, VOC_, VOC_, m0, n0, acc);

    const int tid = threadIdx.x;
    const int ty = tid >> 3, tx = tid & 7;
    #pragma unroll
    for (int r = 0; r < 4; r++) {
        const int row = m0 + (ty << 2) + r;   // row = t*B + b
        const int tt = row >> 7;
        const int bb = row & (B_ - 1);
        const size_t obase = (size_t)(bb * T_ + tt) * VOC_;
        #pragma unroll
        for (int cp = 0; cp < 4; cp++) {
            const float2 v = upk(acc[r][cp]);
            const float vv[2] = {v.x, v.y};
            #pragma unroll
            for (int s = 0; s < 2; s++) {
                const int c = n0 + (tx << 3) + (cp << 1) + s;
                if (c < VOC_) out[obase + c] = vv[s] + bo[c];
            }
        }
    }
}

// ---------------- embedding gather ------------------------------------------
__global__ void k_embed(const float* __restrict__ emb, const int* __restrict__ tok)
{
    const int i = blockIdx.x * 256 + threadIdx.x;      // float4 index
    if (i >= MB_ * (HID_ / 4)) return;
    const int e4 = i & 127;
    const int tb = i >> 7;                             // t*B + b
    const int t = tb >> 7;
    const int b = tb & (B_ - 1);
    const int tk = tok[b * T_ + t];
    ((float4*)g_X)[i] = ((const float4*)emb)[(size_t)tk * (HID_ / 4) + e4];
}

// ---------------- final state copy ------------------------------------------
__global__ void k_state(float* __restrict__ out)
{
    const int i = blockIdx.x * 256 + threadIdx.x;
    if (i >= B_ * HID_) return;
    out[LOGITS_ELEMS + i]             = g_s0[i];
    out[LOGITS_ELEMS + B_ * HID_ + i] = g_s1[i];
}

// ---------------- launch -----------------------------------------------------
extern "C" void kernel_launch(void* const* d_in, const int* in_sizes, int n_in,
                              void* d_out, int out_size)
{
    const float* vgg  = (const float*)d_in[0];
    const int*   tok  = (const int*)  d_in[1];
    // d_in[2] = is_train (unused)
    const float* emb  = (const float*)d_in[3];
    const float* W_in = (const float*)d_in[4];
    const float* b_in = (const float*)d_in[5];
    const float* Wu0  = (const float*)d_in[6];
    const float* bu0  = (const float*)d_in[7];
    const float* Wr0  = (const float*)d_in[8];
    const float* br0  = (const float*)d_in[9];
    const float* Wc0  = (const float*)d_in[10];
    const float* bc0  = (const float*)d_in[11];
    const float* Wu1  = (const float*)d_in[12];
    const float* bu1  = (const float*)d_in[13];
    const float* Wr1  = (const float*)d_in[14];
    const float* br1  = (const float*)d_in[15];
    const float* Wc1  = (const float*)d_in[16];
    const float* bc1  = (const float*)d_in[17];
    const float* Wo   = (const float*)d_in[18];
    const float* bo   = (const float*)d_in[19];
    float* out = (float*)d_out;

    void *pS0, *pS1, *pSeq, *pGrh, *pP;
    cudaGetSymbolAddress(&pS0,  g_s0);
    cudaGetSymbolAddress(&pS1,  g_s1);
    cudaGetSymbolAddress(&pSeq, g_seq);
    cudaGetSymbolAddress(&pGrh, g_grh);
    cudaGetSymbolAddress(&pP,   g_P);
    float* s0  = (float*)pS0;
    float* s1  = (float*)pS1;
    float* seq = (float*)pSeq;
    float* grh = (float*)pGrh;
    float* P   = (float*)pP;

    k_embed<<<(MB_ * (HID_ / 4) + 255) / 256, 256>>>(emb, tok);
    k_prec<<<dim3(MB_ / 64, HID_ / 64, 3), 128>>>(Wu0, Wr0, Wc0);
    k_h0<<<dim3(B_ / 32, HID_ / 32), 256>>>(vgg, W_in, b_in);

    const dim3 gGates(B_ / 32, (2 * HID_) / 32);   // 4 x 32 = 128 CTAs
    const dim3 gCand (B_ / 32, HID_ / 32);         // 4 x 16 =  64 CTAs
    const size_t plane = (size_t)MB_ * HID_;
    const float* Wu0h = Wu0 + (size_t)HID_ * HID_;  // h-part rows of layer-0 W
    const float* Wr0h = Wr0 + (size_t)HID_ * HID_;
    const float* Wc0h = Wc0 + (size_t)HID_ * HID_;

    for (int t = 0; t < T_; t++) {
        const float* Pu = P + 0 * plane + (size_t)t * B_ * HID_;
        const float* Pr = P + 1 * plane + (size_t)t * B_ * HID_;
        const float* Pc = P + 2 * plane + (size_t)t * B_ * HID_;
        // layer 0: K = 512 (h only; x-part precomputed)
        k_gates<4><<<gGates, 256>>>(s0, s0, HID_, Wu0h, bu0, Wr0h, br0, Pu, Pr, s0);
        k_cand <4><<<gCand, 256>>>(grh, grh, HID_, Wc0h, bc0, Pc, s0, (float*)0);
        // layer 1: K = 1024 ([x=s0 | h=s1])
        k_gates<8><<<gGates, 256>>>(s0, s1, HID_, Wu1, bu1, Wr1, br1, (float*)0, (float*)0, s1);
        k_cand <8><<<gCand, 256>>>(s0, grh, HID_, Wc1, bc1, (float*)0, s1,
                                   seq + (size_t)t * B_ * HID_);
    }

    k_logits<<<dim3(MB_ / 64, (VOC_ + 63) / 64), 128>>>(Wo, bo, out);
    if (out_size >= LOGITS_ELEMS + STATE_ELEMS)
        k_state<<<(B_ * HID_ + 255) / 256, 256>>>(out);
}

// round 15
// speedup vs baseline: 1.8263x; 1.0522x over previous
#include <cuda_runtime.h>
#include <math.h>

#define B_    128
#define T_    25
#define HID_  512
#define VOC_  10000
#define VGG_  4096
#define MB_   (T_ * B_)                 // 3200 rows of X / seq
#define LOGITS_ELEMS (B_ * T_ * VOC_)
#define STATE_ELEMS  (2 * B_ * HID_)

typedef unsigned long long ull;

// ---------------- scratch (device globals; no allocation allowed) -----------
__device__ float g_X   [MB_ * HID_];      // embedded tokens [t*B+b][e]
__device__ float g_P   [3 * MB_ * HID_];  // precomputed x-projections (u,r,c)
__device__ float g_s0a [B_ * HID_];       // layer-0 hidden, parity-0 buffer
__device__ float g_s0b [B_ * HID_];       // layer-0 hidden, parity-1 buffer
__device__ float g_s1  [B_ * HID_];       // layer-1 hidden
__device__ float g_gu0 [B_ * HID_];       // layer-0 update gate
__device__ float g_grh0[B_ * HID_];       // layer-0 reset*h
__device__ float g_gu1 [B_ * HID_];       // layer-1 update gate
__device__ float g_grh1[B_ * HID_];       // layer-1 reset*h
__device__ float g_seq [MB_ * HID_];      // all layer-1 states

// ---------------- packed f32x2 helpers --------------------------------------
__device__ __forceinline__ ull pk2(float x) {
    ull r; asm("mov.b64 %0, {%1, %1};" : "=l"(r) : "f"(x)); return r;
}
__device__ __forceinline__ void fma2(ull& c, ull a, ull b) {
    asm("fma.rn.f32x2 %0, %1, %2, %0;" : "+l"(c) : "l"(a), "l"(b));
}
__device__ __forceinline__ ull add2(ull a, ull b) {
    ull r; asm("add.rn.f32x2 %0, %1, %2;" : "=l"(r) : "l"(a), "l"(b)); return r;
}
__device__ __forceinline__ float2 upk(ull v) {
    float2 r; asm("mov.b64 {%0, %1}, %2;" : "=f"(r.x), "=f"(r.y) : "l"(v)); return r;
}
__device__ __forceinline__ float sigf(float z) { return 1.0f / (1.0f + expf(-z)); }

// ============================================================================
// Recurrence GEMM core — R14's measured-good flat-dump version with RUNTIME
// nchunk and caller-scope smem (so two differently-shaped GEMMs can share one
// kernel / one 34KB smem buffer). On return every thread holds the summed
// f32x2 pair for 4 consecutive output columns of one row (see epi_coord).
// ============================================================================
#define DUMP17 (8 * 32 * 17)            // padded dump region (4352 ull = 34KB)

__device__ __forceinline__ void rec_gemm_rt(
    int nchunk, ull* sraw,
    const float* __restrict__ A0, int lda0, int ka0,
    const float* __restrict__ A1, int lda1,
    const float* __restrict__ W,  int ldw,
    int m0, int n0, ull out[2])
{
    const int tid  = threadIdx.x;
    const int g    = tid >> 5;
    const int lane = tid & 31;
    const int ty   = lane >> 2;
    const int tx   = lane & 3;
    const int KG   = nchunk << 4;

    float* Af = (float*)(sraw + g * 256);          // [16 kk][32 row] = 2KB
    float* Bf = (float*)(sraw + 2048 + g * 256);   // [16 kk][32 col] = 2KB
    ull*   Bu = (ull*)Bf;

    ull acc[4][4];
    #pragma unroll
    for (int r = 0; r < 4; r++)
        #pragma unroll
        for (int c = 0; c < 4; c++) acc[r][c] = 0ULL;

    float4 pa[4], pb[4];
    auto loadc = [&](int c) {
        const int kb = g * KG + (c << 4);
        const float* A; int lda, ka;
        if (kb < ka0) { A = A0; lda = lda0; ka = kb; }
        else          { A = A1; lda = lda1; ka = kb - ka0; }
        #pragma unroll
        for (int i = 0; i < 4; i++) {
            const int idx = lane * 4 + i;
            pa[i] = *(const float4*)(A + (size_t)(m0 + (idx >> 2)) * lda + ka + ((idx & 3) << 2));
            pb[i] = *(const float4*)(W + (size_t)(kb + (idx >> 3)) * ldw + n0 + ((idx & 7) << 2));
        }
    };

    loadc(0);
    #pragma unroll 1
    for (int c = 0; c < nchunk; c++) {
        #pragma unroll
        for (int i = 0; i < 4; i++) {
            const int idx = lane * 4 + i;
            const int row = idx >> 2, kc = (idx & 3) << 2;
            Af[(kc + 0) * 32 + row] = pa[i].x;
            Af[(kc + 1) * 32 + row] = pa[i].y;
            Af[(kc + 2) * 32 + row] = pa[i].z;
            Af[(kc + 3) * 32 + row] = pa[i].w;
            *(float4*)&Bf[(idx >> 3) * 32 + ((idx & 7) << 2)] = pb[i];
        }
        __syncthreads();
        if (c + 1 < nchunk) loadc(c + 1);
        #pragma unroll
        for (int kk = 0; kk < 16; kk++) {
            const float4 a = *(const float4*)&Af[kk * 32 + (ty << 2)];
            const ull b0 = Bu[kk * 16 + tx * 4 + 0];
            const ull b1 = Bu[kk * 16 + tx * 4 + 1];
            const ull b2 = Bu[kk * 16 + tx * 4 + 2];
            const ull b3 = Bu[kk * 16 + tx * 4 + 3];
            ull ar;
            ar = pk2(a.x);
            fma2(acc[0][0], ar, b0); fma2(acc[0][1], ar, b1);
            fma2(acc[0][2], ar, b2); fma2(acc[0][3], ar, b3);
            ar = pk2(a.y);
            fma2(acc[1][0], ar, b0); fma2(acc[1][1], ar, b1);
            fma2(acc[1][2], ar, b2); fma2(acc[1][3], ar, b3);
            ar = pk2(a.z);
            fma2(acc[2][0], ar, b0); fma2(acc[2][1], ar, b1);
            fma2(acc[2][2], ar, b2); fma2(acc[2][3], ar, b3);
            ar = pk2(a.w);
            fma2(acc[3][0], ar, b0); fma2(acc[3][1], ar, b1);
            fma2(acc[3][2], ar, b2); fma2(acc[3][3], ar, b3);
        }
        __syncthreads();
    }

    // flat dump (stride-17 pad) -> one barrier -> every thread gathers its
    // 2 ull (= 4 consecutive output columns) summed over the 8 k-groups.
    {
        ull* p = sraw + (size_t)((g << 5) + lane) * 17;
        #pragma unroll
        for (int r = 0; r < 4; r++)
            #pragma unroll
            for (int c = 0; c < 4; c++) p[r * 4 + c] = acc[r][c];
    }
    __syncthreads();
    {
        const int L = tid >> 3;
        const int j0 = (tid & 7) << 1;
        ull s0 = 0ULL, s1 = 0ULL;
        #pragma unroll
        for (int ww = 0; ww < 8; ww++) {
            const ull* p = sraw + (size_t)((ww << 5) + L) * 17 + j0;
            s0 = add2(s0, p[0]);
            s1 = add2(s1, p[1]);
        }
        out[0] = s0;
        out[1] = s1;
    }
}

// Per-thread output coordinates for the flat epilogue (R14-verified mapping).
__device__ __forceinline__ void epi_coord(int m0, int n0, int& row, int& col)
{
    const int tid = threadIdx.x;
    const int L  = tid >> 3;
    const int j0 = (tid & 7) << 1;
    row = m0 + ((L >> 2) << 2) + (j0 >> 2);
    col = n0 + ((L & 3) << 3) + ((j0 & 3) << 1);
}

// ============================================================================
// FUSED gates kernel: side A = layer-0 gates(t+1) (K=512, +P terms),
// side B = layer-1 gates(t) (K=1024, concat [s0|s1]). CTAs [0,nA) run A,
// [nA, nA+nB) run B. Per side: 128 CTAs = 4 m-tiles x 32 combined u|r tiles.
// ============================================================================
__global__ __launch_bounds__(256) void k_gatesF(
    int nA,
    const float* __restrict__ aA,
    const float* __restrict__ WuA, const float* __restrict__ buA,
    const float* __restrict__ WrA, const float* __restrict__ brA,
    const float* __restrict__ PuA, const float* __restrict__ PrA,
    const float* __restrict__ hA,
    float* __restrict__ guA, float* __restrict__ grhA,
    const float* __restrict__ a0B, const float* __restrict__ a1B,
    const float* __restrict__ WuB, const float* __restrict__ buB,
    const float* __restrict__ WrB, const float* __restrict__ brB,
    const float* __restrict__ hB,
    float* __restrict__ guB, float* __restrict__ grhB)
{
    __shared__ __align__(16) ull sraw[DUMP17];
    const int cta   = blockIdx.x;
    const bool isA  = cta < nA;
    const int local = isA ? cta : cta - nA;
    const int m0 = (local & 3) * 32;
    const int nc = (local >> 2) * 32;
    const bool isU = nc < HID_;
    const int n0 = isU ? nc : nc - HID_;

    ull o[2];
    const float *bias, *P, *h;
    float *gu, *grh;
    if (isA) {
        bias = isU ? buA : brA;  P = isU ? PuA : PrA;
        h = hA; gu = guA; grh = grhA;
        rec_gemm_rt(4, sraw, aA, HID_, 2 * HID_, aA, HID_,
                    isU ? WuA : WrA, HID_, m0, n0, o);
    } else {
        bias = isU ? buB : brB;  P = 0;
        h = hB; gu = guB; grh = grhB;
        rec_gemm_rt(8, sraw, a0B, HID_, HID_, a1B, HID_,
                    isU ? WuB : WrB, HID_, m0, n0, o);
    }

    int row, col;
    epi_coord(m0, n0, row, col);
    const float2 v0 = upk(o[0]);
    const float2 v1 = upk(o[1]);
    const float4 bb = *(const float4*)&bias[col];
    float4 val = make_float4(v0.x + bb.x, v0.y + bb.y, v1.x + bb.z, v1.y + bb.w);
    if (P) {
        const float4 pp = *(const float4*)&P[row * HID_ + col];
        val.x += pp.x; val.y += pp.y; val.z += pp.z; val.w += pp.w;
    }
    val.x = sigf(val.x); val.y = sigf(val.y);
    val.z = sigf(val.z); val.w = sigf(val.w);
    if (isU) {
        *(float4*)&gu[row * HID_ + col] = val;
    } else {
        const float4 hh = *(const float4*)&h[row * HID_ + col];
        val.x *= hh.x; val.y *= hh.y; val.z *= hh.z; val.w *= hh.w;
        *(float4*)&grh[row * HID_ + col] = val;
    }
}

// ============================================================================
// FUSED candidate kernel: side A = layer-0 cand(t+1) (K=512 over grh0, +Pc,
// hin s0cur -> hout s0next), side B = layer-1 cand(t) (K=1024 over [s0|grh1],
// h = s1 in/out, writes seq). Per side: 64 CTAs = 4 m x 16 n.
// ============================================================================
__global__ __launch_bounds__(256) void k_candF(
    int nA,
    const float* __restrict__ aA, const float* __restrict__ WcA,
    const float* __restrict__ bcA, const float* __restrict__ PcA,
    const float* __restrict__ guA,
    const float* __restrict__ hinA, float* __restrict__ houtA,
    const float* __restrict__ a0B, const float* __restrict__ a1B,
    const float* __restrict__ WcB, const float* __restrict__ bcB,
    const float* __restrict__ guB,
    float* __restrict__ hB, float* __restrict__ seqB)
{
    __shared__ __align__(16) ull sraw[DUMP17];
    const int cta   = blockIdx.x;
    const bool isA  = cta < nA;
    const int local = isA ? cta : cta - nA;
    const int m0 = (local & 3) * 32;
    const int n0 = (local >> 2) * 32;

    ull o[2];
    const float *bc, *Pc, *gu, *hin;
    float *hout, *seq;
    if (isA) {
        bc = bcA; Pc = PcA; gu = guA; hin = hinA; hout = houtA; seq = 0;
        rec_gemm_rt(4, sraw, aA, HID_, 2 * HID_, aA, HID_, WcA, HID_, m0, n0, o);
    } else {
        bc = bcB; Pc = 0; gu = guB; hin = hB; hout = hB; seq = seqB;
        rec_gemm_rt(8, sraw, a0B, HID_, HID_, a1B, HID_, WcB, HID_, m0, n0, o);
    }

    int row, col;
    epi_coord(m0, n0, row, col);
    const float2 v0 = upk(o[0]);
    const float2 v1 = upk(o[1]);
    const float4 bb = *(const float4*)&bc[col];
    float4 val = make_float4(v0.x + bb.x, v0.y + bb.y, v1.x + bb.z, v1.y + bb.w);
    if (Pc) {
        const float4 pp = *(const float4*)&Pc[row * HID_ + col];
        val.x += pp.x; val.y += pp.y; val.z += pp.z; val.w += pp.w;
    }
    const float4 gg = *(const float4*)&gu[row * HID_ + col];
    const float4 hh = *(const float4*)&hin[row * HID_ + col];
    float4 hn;
    hn.x = gg.x * hh.x + (1.0f - gg.x) * tanhf(val.x);
    hn.y = gg.y * hh.y + (1.0f - gg.y) * tanhf(val.y);
    hn.z = gg.z * hh.z + (1.0f - gg.z) * tanhf(val.z);
    hn.w = gg.w * hh.w + (1.0f - gg.w) * tanhf(val.w);
    *(float4*)&hout[row * HID_ + col] = hn;
    if (seq) *(float4*)&seq[row * HID_ + col] = hn;
}

// ---------------- h0 = tanh(vgg @ W_in + b_in) -> s0 parity-1 buf + s1 ------
__global__ __launch_bounds__(256) void k_h0(
    const float* __restrict__ vgg, const float* __restrict__ W_in,
    const float* __restrict__ b_in,
    float* __restrict__ s0out, float* __restrict__ s1out)
{
    __shared__ __align__(16) ull sraw[DUMP17];
    const int m0 = blockIdx.x * 32;
    const int n0 = blockIdx.y * 32;

    ull o[2];
    rec_gemm_rt(32, sraw, vgg, VGG_, VGG_, vgg, VGG_, W_in, HID_, m0, n0, o);

    int row, col;
    epi_coord(m0, n0, row, col);
    const float2 v0 = upk(o[0]);
    const float2 v1 = upk(o[1]);
    const float4 bb = *(const float4*)&b_in[col];
    float4 val;
    val.x = tanhf(v0.x + bb.x);
    val.y = tanhf(v0.y + bb.y);
    val.z = tanhf(v1.x + bb.z);
    val.w = tanhf(v1.y + bb.w);
    *(float4*)&s0out[row * HID_ + col] = val;
    *(float4*)&s1out[row * HID_ + col] = val;
}

// ============================================================================
// Big parallel GEMM core: 64x64 tile, 128 threads, micro-tile 4x8 (unchanged).
// ============================================================================
template <bool GUARD>
__device__ __forceinline__ void big_gemm(
    const float* __restrict__ A, int lda,
    const float* __restrict__ W, int ldw, int nmax,
    int m0, int n0, ull acc[4][4])
{
    __shared__ __align__(16) float As[16][64];
    __shared__ __align__(16) float Bs[16][64];
    const int tid = threadIdx.x;
    const int ty = tid >> 3, tx = tid & 7;

    #pragma unroll
    for (int r = 0; r < 4; r++)
        #pragma unroll
        for (int c = 0; c < 4; c++) acc[r][c] = 0ULL;

    float4 pa[2], pb[2];
    auto loadc = [&](int k0) {
        #pragma unroll
        for (int i = 0; i < 2; i++) {
            const int idx = tid * 2 + i;
            pa[i] = *(const float4*)(A + (size_t)(m0 + (idx >> 2)) * lda + k0 + ((idx & 3) << 2));
            const int kr = idx >> 4, c4 = (idx & 15) << 2;
            const int gc = n0 + c4;
            const float* Wr = W + (size_t)(k0 + kr) * ldw;
            if (!GUARD || gc + 3 < nmax) {
                pb[i] = *(const float4*)(Wr + gc);
            } else {
                pb[i].x = (gc + 0 < nmax) ? Wr[gc + 0] : 0.0f;
                pb[i].y = (gc + 1 < nmax) ? Wr[gc + 1] : 0.0f;
                pb[i].z = (gc + 2 < nmax) ? Wr[gc + 2] : 0.0f;
                pb[i].w = (gc + 3 < nmax) ? Wr[gc + 3] : 0.0f;
            }
        }
    };

    loadc(0);
    for (int k0 = 0; k0 < HID_; k0 += 16) {
        #pragma unroll
        for (int i = 0; i < 2; i++) {
            const int idx = tid * 2 + i;
            const int row = idx >> 2, kc = (idx & 3) << 2;
            As[kc + 0][row] = pa[i].x;
            As[kc + 1][row] = pa[i].y;
            As[kc + 2][row] = pa[i].z;
            As[kc + 3][row] = pa[i].w;
            *(float4*)&Bs[idx >> 4][(idx & 15) << 2] = pb[i];
        }
        __syncthreads();
        if (k0 + 16 < HID_) loadc(k0 + 16);
        #pragma unroll
        for (int kk = 0; kk < 16; kk++) {
            const float4 a = *(const float4*)&As[kk][ty << 2];
            const ull* br = (const ull*)Bs[kk];
            const ull b0 = br[tx * 4 + 0], b1 = br[tx * 4 + 1];
            const ull b2 = br[tx * 4 + 2], b3 = br[tx * 4 + 3];
            ull ar;
            ar = pk2(a.x);
            fma2(acc[0][0], ar, b0); fma2(acc[0][1], ar, b1);
            fma2(acc[0][2], ar, b2); fma2(acc[0][3], ar, b3);
            ar = pk2(a.y);
            fma2(acc[1][0], ar, b0); fma2(acc[1][1], ar, b1);
            fma2(acc[1][2], ar, b2); fma2(acc[1][3], ar, b3);
            ar = pk2(a.z);
            fma2(acc[2][0], ar, b0); fma2(acc[2][1], ar, b1);
            fma2(acc[2][2], ar, b2); fma2(acc[2][3], ar, b3);
            ar = pk2(a.w);
            fma2(acc[3][0], ar, b0); fma2(acc[3][1], ar, b1);
            fma2(acc[3][2], ar, b2); fma2(acc[3][3], ar, b3);
        }
        __syncthreads();
    }
}

// ---------------- precompute: P[z] = X @ Wz[0:512]  (z = u0, r0, c0) --------
__global__ __launch_bounds__(128) void k_prec(
    const float* __restrict__ Wu0, const float* __restrict__ Wr0,
    const float* __restrict__ Wc0)
{
    const int z = blockIdx.z;
    const float* W = (z == 0) ? Wu0 : ((z == 1) ? Wr0 : Wc0);
    float* outp = g_P + (size_t)z * MB_ * HID_;
    const int m0 = blockIdx.x * 64;
    const int n0 = blockIdx.y * 64;

    ull acc[4][4];
    big_gemm<false>(g_X, HID_, W, HID_, HID_, m0, n0, acc);

    const int tid = threadIdx.x;
    const int ty = tid >> 3, tx = tid & 7;
    #pragma unroll
    for (int r = 0; r < 4; r++) {
        const int row = m0 + (ty << 2) + r;
        #pragma unroll
        for (int cp = 0; cp < 4; cp++) {
            const float2 v = upk(acc[r][cp]);
            const int c = n0 + (tx << 3) + (cp << 1);
            outp[(size_t)row * HID_ + c]     = v.x;
            outp[(size_t)row * HID_ + c + 1] = v.y;
        }
    }
}

// ---------------- logits: g_seq[3200,512] @ W_out[512,10000] + b_out --------
__global__ __launch_bounds__(128) void k_logits(
    const float* __restrict__ Wo, const float* __restrict__ bo,
    float* __restrict__ out)
{
    const int m0 = blockIdx.x * 64;
    const int n0 = blockIdx.y * 64;

    ull acc[4][4];
    big_gemm<true>(g_seq, HID_, Wo, VOC_, VOC_, m0, n0, acc);

    const int tid = threadIdx.x;
    const int ty = tid >> 3, tx = tid & 7;
    #pragma unroll
    for (int r = 0; r < 4; r++) {
        const int row = m0 + (ty << 2) + r;   // row = t*B + b
        const int tt = row >> 7;
        const int bb = row & (B_ - 1);
        const size_t obase = (size_t)(bb * T_ + tt) * VOC_;
        #pragma unroll
        for (int cp = 0; cp < 4; cp++) {
            const float2 v = upk(acc[r][cp]);
            const float vv[2] = {v.x, v.y};
            #pragma unroll
            for (int s = 0; s < 2; s++) {
                const int c = n0 + (tx << 3) + (cp << 1) + s;
                if (c < VOC_) out[obase + c] = vv[s] + bo[c];
            }
        }
    }
}

// ---------------- embedding gather ------------------------------------------
__global__ void k_embed(const float* __restrict__ emb, const int* __restrict__ tok)
{
    const int i = blockIdx.x * 256 + threadIdx.x;      // float4 index
    if (i >= MB_ * (HID_ / 4)) return;
    const int e4 = i & 127;
    const int tb = i >> 7;                             // t*B + b
    const int t = tb >> 7;
    const int b = tb & (B_ - 1);
    const int tk = tok[b * T_ + t];
    ((float4*)g_X)[i] = ((const float4*)emb)[(size_t)tk * (HID_ / 4) + e4];
}

// ---------------- final state copy ------------------------------------------
__global__ void k_state(float* __restrict__ out, const float* __restrict__ s0fin)
{
    const int i = blockIdx.x * 256 + threadIdx.x;
    if (i >= B_ * HID_) return;
    out[LOGITS_ELEMS + i]             = s0fin[i];
    out[LOGITS_ELEMS + B_ * HID_ + i] = g_s1[i];
}

// ---------------- launch -----------------------------------------------------
extern "C" void kernel_launch(void* const* d_in, const int* in_sizes, int n_in,
                              void* d_out, int out_size)
{
    const float* vgg  = (const float*)d_in[0];
    const int*   tok  = (const int*)  d_in[1];
    // d_in[2] = is_train (unused)
    const float* emb  = (const float*)d_in[3];
    const float* W_in = (const float*)d_in[4];
    const float* b_in = (const float*)d_in[5];
    const float* Wu0  = (const float*)d_in[6];
    const float* bu0  = (const float*)d_in[7];
    const float* Wr0  = (const float*)d_in[8];
    const float* br0  = (const float*)d_in[9];
    const float* Wc0  = (const float*)d_in[10];
    const float* bc0  = (const float*)d_in[11];
    const float* Wu1  = (const float*)d_in[12];
    const float* bu1  = (const float*)d_in[13];
    const float* Wr1  = (const float*)d_in[14];
    const float* br1  = (const float*)d_in[15];
    const float* Wc1  = (const float*)d_in[16];
    const float* bc1  = (const float*)d_in[17];
    const float* Wo   = (const float*)d_in[18];
    const float* bo   = (const float*)d_in[19];
    float* out = (float*)d_out;

    void *pS0a, *pS0b, *pS1, *pSeq, *pGu0, *pGrh0, *pGu1, *pGrh1, *pP;
    cudaGetSymbolAddress(&pS0a,  g_s0a);
    cudaGetSymbolAddress(&pS0b,  g_s0b);
    cudaGetSymbolAddress(&pS1,   g_s1);
    cudaGetSymbolAddress(&pSeq,  g_seq);
    cudaGetSymbolAddress(&pGu0,  g_gu0);
    cudaGetSymbolAddress(&pGrh0, g_grh0);
    cudaGetSymbolAddress(&pGu1,  g_gu1);
    cudaGetSymbolAddress(&pGrh1, g_grh1);
    cudaGetSymbolAddress(&pP,    g_P);
    float* s0buf[2] = {(float*)pS0a, (float*)pS0b};
    float* s1   = (float*)pS1;
    float* seq  = (float*)pSeq;
    float* gu0  = (float*)pGu0;
    float* grh0 = (float*)pGrh0;
    float* gu1  = (float*)pGu1;
    float* grh1 = (float*)pGrh1;
    float* P    = (float*)pP;

    k_embed<<<(MB_ * (HID_ / 4) + 255) / 256, 256>>>(emb, tok);
    k_prec<<<dim3(MB_ / 64, HID_ / 64, 3), 128>>>(Wu0, Wr0, Wc0);
    // h0 -> state s0(-1) lives in parity-1 buffer
    k_h0<<<dim3(B_ / 32, HID_ / 32), 256>>>(vgg, W_in, b_in, s0buf[1], s1);

    const size_t plane = (size_t)MB_ * HID_;
    const float* Wu0h = Wu0 + (size_t)HID_ * HID_;  // h-part rows of layer-0 W
    const float* Wr0h = Wr0 + (size_t)HID_ * HID_;
    const float* Wc0h = Wc0 + (size_t)HID_ * HID_;
    auto Pu = [&](int t) { return P + 0 * plane + (size_t)t * B_ * HID_; };
    auto Pr = [&](int t) { return P + 1 * plane + (size_t)t * B_ * HID_; };
    auto Pc = [&](int t) { return P + 2 * plane + (size_t)t * B_ * HID_; };

    // ---- prologue: gates0(0), cand0(0). s0(-1)=buf[1] -> s0(0)=buf[0] ----
    k_gatesF<<<128, 256>>>(128,
        s0buf[1], Wu0h, bu0, Wr0h, br0, Pu(0), Pr(0), s0buf[1], gu0, grh0,
        (float*)0, (float*)0, (float*)0, (float*)0, (float*)0, (float*)0,
        (float*)0, (float*)0, (float*)0);
    k_candF<<<64, 256>>>(64,
        grh0, Wc0h, bc0, Pc(0), gu0, s0buf[1], s0buf[0],
        (float*)0, (float*)0, (float*)0, (float*)0, (float*)0,
        (float*)0, (float*)0);

    // ---- main loop: X(t) = gates0(t+1) || gates1(t); Y(t) = cand0(t+1) ||
    //      cand1(t). s0(t) = buf[t&1]. ----
    for (int t = 0; t < T_; t++) {
        float* s0cur  = s0buf[t & 1];
        float* s0next = s0buf[(t + 1) & 1];
        const int nAg = (t < T_ - 1) ? 128 : 0;
        const int nAc = (t < T_ - 1) ? 64 : 0;

        k_gatesF<<<nAg + 128, 256>>>(nAg,
            s0cur, Wu0h, bu0, Wr0h, br0, Pu(t + 1), Pr(t + 1), s0cur, gu0, grh0,
            s0cur, s1, Wu1, bu1, Wr1, br1, s1, gu1, grh1);

        k_candF<<<nAc + 64, 256>>>(nAc,
            grh0, Wc0h, bc0, Pc(t + 1), gu0, s0cur, s0next,
            s0cur, grh1, Wc1, bc1, gu1, s1, seq + (size_t)t * B_ * HID_);
    }

    k_logits<<<dim3(MB_ / 64, (VOC_ + 63) / 64), 128>>>(Wo, bo, out);
    if (out_size >= LOGITS_ELEMS + STATE_ELEMS)
        k_state<<<(B_ * HID_ + 255) / 256, 256>>>(out, s0buf[(T_ - 1) & 1]);
}